// round 10
// baseline (speedup 1.0000x reference)
#include <cuda_runtime.h>
#include <cstdint>

// LSTM: B x T x I -> last hidden -> FC.  I=4, H=8, O=1, T=512.
// Round-10 = Round-4 (best, 100.9us) with ONE change: the four gate
// activations run as 2x tanh.approx.f16x2 (packed) instead of 4x f32 tanh.
// Theory: hidden MUFU.TANH throughput wall (rt~16/SMSP) -> 5.24M tanh ops
// = 75us floor across R4/R6/R9. This cuts MUFU ops/step 5 -> 3.
// tanh(c) stays f32 (c accumulates; keep its chain exact).
// Kept: 8 lanes/batch, 2048 warps, gate-pair f32x2, folded 0.5 scales,
// 4-deep x prefetch.

#define T_SEQ 512
#define IDIM  4
#define HDIM  8

typedef unsigned long long u64;

__device__ __forceinline__ u64 pack2(float a, float b) {
    u64 r; asm("mov.b64 %0,{%1,%2};" : "=l"(r) : "f"(a), "f"(b)); return r;
}
__device__ __forceinline__ u64 dup2(float a) {
    u64 r; asm("mov.b64 %0,{%1,%1};" : "=l"(r) : "f"(a)); return r;
}
__device__ __forceinline__ float2 unpack2(u64 v) {
    float2 r; asm("mov.b64 {%0,%1},%2;" : "=f"(r.x), "=f"(r.y) : "l"(v)); return r;
}
__device__ __forceinline__ u64 fma2(u64 a, u64 b, u64 c) {
    u64 d; asm("fma.rn.f32x2 %0,%1,%2,%3;" : "=l"(d) : "l"(a), "l"(b), "l"(c)); return d;
}
__device__ __forceinline__ u64 mul2(u64 a, u64 b) {
    u64 d; asm("mul.rn.f32x2 %0,%1,%2;" : "=l"(d) : "l"(a), "l"(b)); return d;
}
__device__ __forceinline__ u64 add2(u64 a, u64 b) {
    u64 d; asm("add.rn.f32x2 %0,%1,%2;" : "=l"(d) : "l"(a), "l"(b)); return d;
}
__device__ __forceinline__ float tanh_fast(float x) {
    float y; asm("tanh.approx.f32 %0,%1;" : "=f"(y) : "f"(x)); return y;
}

__global__ __launch_bounds__(64)
void lstm_fused_kernel(const float* __restrict__ x,
                       const float* __restrict__ W_ih,
                       const float* __restrict__ W_hh,
                       const float* __restrict__ b_ih,
                       const float* __restrict__ b_hh,
                       const float* __restrict__ W_fc,
                       const float* __restrict__ b_fc,
                       float* __restrict__ out,
                       int B)
{
    const int tid = threadIdx.x;
    const int j   = tid & 7;                        // hidden unit owned by this lane
    int b = blockIdx.x * 8 + (tid >> 3);            // batch element
    const bool valid = (b < B);
    if (b >= B) b = B - 1;                          // clamp: keep warp converged

    // ---- per-lane weights, packed over gate pairs (i,f)/(g,o); sigmoid gates
    // (i,f,o) pre-scaled by 0.5 so sigmoid(z) = 0.5*tanh(acc)+0.5 directly.
    u64 wih01[IDIM], wih23[IDIM];
    u64 whh01[HDIM], whh23[HDIM];
    u64 bias01, bias23;
    {
        const int r0 = 0 * HDIM + j;   // i
        const int r1 = 1 * HDIM + j;   // f
        const int r2 = 2 * HDIM + j;   // g
        const int r3 = 3 * HDIM + j;   // o
#pragma unroll
        for (int m = 0; m < IDIM; ++m) {
            wih01[m] = pack2(0.5f * W_ih[r0 * IDIM + m], 0.5f * W_ih[r1 * IDIM + m]);
            wih23[m] = pack2(        W_ih[r2 * IDIM + m], 0.5f * W_ih[r3 * IDIM + m]);
        }
#pragma unroll
        for (int k = 0; k < HDIM; ++k) {
            whh01[k] = pack2(0.5f * W_hh[r0 * HDIM + k], 0.5f * W_hh[r1 * HDIM + k]);
            whh23[k] = pack2(        W_hh[r2 * HDIM + k], 0.5f * W_hh[r3 * HDIM + k]);
        }
        bias01 = pack2(0.5f * (b_ih[r0] + b_hh[r0]), 0.5f * (b_ih[r1] + b_hh[r1]));
        bias23 = pack2(        b_ih[r2] + b_hh[r2],  0.5f * (b_ih[r3] + b_hh[r3]));
    }

    const float4* __restrict__ xp =
        reinterpret_cast<const float4*>(x) + (size_t)b * T_SEQ;

    float h = 0.0f, c = 0.0f;

    // half2 activation constants
    const uint32_t K_05_05 = 0x38003800u;   // (hi=0.5, lo=0.5)
    const uint32_t K_MULGO = 0x38003C00u;   // hi=0.5 (o), lo=1.0 (g)
    const uint32_t K_ADDGO = 0x38000000u;   // hi=0.5 (o), lo=0.0 (g)

    // rolling 4-step prefetch buffer (covers DRAM miss latency, MLP=4)
    float4 buf0 = xp[0], buf1 = xp[1], buf2 = xp[2], buf3 = xp[3];

#pragma unroll 1
    for (int t0 = 0; t0 < T_SEQ; t0 += 4) {
        const int tn = (t0 + 4) & (T_SEQ - 1);      // wraps on last iter (harmless)
        const float4 n0 = xp[tn + 0];
        const float4 n1 = xp[tn + 1];
        const float4 n2 = xp[tn + 2];
        const float4 n3 = xp[tn + 3];

        const float4 bufs[4] = {buf0, buf1, buf2, buf3};
#pragma unroll
        for (int u = 0; u < 4; ++u) {
            const float4 xc = bufs[u];

            // ---- input projection + bias (h-independent) ----
            const u64 d0 = dup2(xc.x), d1 = dup2(xc.y), d2 = dup2(xc.z), d3 = dup2(xc.w);
            u64 p01 = fma2(wih01[0], d0, bias01);
            u64 p23 = fma2(wih23[0], d0, bias23);
            p01 = fma2(wih01[1], d1, p01);  p23 = fma2(wih23[1], d1, p23);
            p01 = fma2(wih01[2], d2, p01);  p23 = fma2(wih23[2], d2, p23);
            p01 = fma2(wih01[3], d3, p01);  p23 = fma2(wih23[3], d3, p23);

            // ---- broadcast h within the 8-lane group ----
            const u64 h0 = dup2(__shfl_sync(0xffffffffu, h, 0, 8));
            const u64 h1 = dup2(__shfl_sync(0xffffffffu, h, 1, 8));
            const u64 h2 = dup2(__shfl_sync(0xffffffffu, h, 2, 8));
            const u64 h3 = dup2(__shfl_sync(0xffffffffu, h, 3, 8));
            const u64 h4 = dup2(__shfl_sync(0xffffffffu, h, 4, 8));
            const u64 h5 = dup2(__shfl_sync(0xffffffffu, h, 5, 8));
            const u64 h6 = dup2(__shfl_sync(0xffffffffu, h, 6, 8));
            const u64 h7 = dup2(__shfl_sync(0xffffffffu, h, 7, 8));

            // ---- recurrent projection, even/odd split ----
            p01 = fma2(whh01[0], h0, p01);  p23 = fma2(whh23[0], h0, p23);
            u64 q01 = mul2(whh01[4], h4);
            u64 q23 = mul2(whh23[4], h4);
            p01 = fma2(whh01[1], h1, p01);  p23 = fma2(whh23[1], h1, p23);
            q01 = fma2(whh01[5], h5, q01);  q23 = fma2(whh23[5], h5, q23);
            p01 = fma2(whh01[2], h2, p01);  p23 = fma2(whh23[2], h2, p23);
            q01 = fma2(whh01[6], h6, q01);  q23 = fma2(whh23[6], h6, q23);
            p01 = fma2(whh01[3], h3, p01);  p23 = fma2(whh23[3], h3, p23);
            q01 = fma2(whh01[7], h7, q01);  q23 = fma2(whh23[7], h7, q23);
            const u64 a01 = add2(p01, q01);     // (zi/2, zf/2)
            const u64 a23 = add2(p23, q23);     // (zg,   zo/2)

            // ---- gate activations: 2x packed f16x2 tanh (MUFU 5 -> 3) ----
            const float2 g01 = unpack2(a01);
            const float2 g23 = unpack2(a23);
            uint32_t pif, pgo;
            asm("cvt.rn.f16x2.f32 %0, %1, %2;" : "=r"(pif) : "f"(g01.y), "f"(g01.x)); // hi=zf', lo=zi'
            asm("cvt.rn.f16x2.f32 %0, %1, %2;" : "=r"(pgo) : "f"(g23.y), "f"(g23.x)); // hi=zo', lo=zg
            uint32_t tif, tgo;
            asm("tanh.approx.f16x2 %0, %1;" : "=r"(tif) : "r"(pif));
            asm("tanh.approx.f16x2 %0, %1;" : "=r"(tgo) : "r"(pgo));
            uint32_t sif, sgo;
            asm("fma.rn.f16x2 %0, %1, %2, %3;" : "=r"(sif)
                : "r"(tif), "r"(K_05_05), "r"(K_05_05));   // (i, f) = 0.5*t+0.5
            asm("fma.rn.f16x2 %0, %1, %2, %3;" : "=r"(sgo)
                : "r"(tgo), "r"(K_MULGO), "r"(K_ADDGO));   // (g, o) = (t, 0.5*t+0.5)
            float ig, fg, gg, og;
            asm("{ .reg .f16 l, h; mov.b32 {l, h}, %2;"
                "  cvt.f32.f16 %0, l; cvt.f32.f16 %1, h; }"
                : "=f"(ig), "=f"(fg) : "r"(sif));
            asm("{ .reg .f16 l, h; mov.b32 {l, h}, %2;"
                "  cvt.f32.f16 %0, l; cvt.f32.f16 %1, h; }"
                : "=f"(gg), "=f"(og) : "r"(sgo));

            // ---- state update (f32; tanh(c) stays exact-path) ----
            c = fmaf(fg, c, ig * gg);
            h = og * tanh_fast(c);
        }

        buf0 = n0; buf1 = n1; buf2 = n2; buf3 = n3;
    }

    // ---- FC head: out[b] = sum_j h_j * W_fc[j] + b_fc ----
    float v = h * __ldg(W_fc + j);
    v += __shfl_xor_sync(0xffffffffu, v, 1, 8);
    v += __shfl_xor_sync(0xffffffffu, v, 2, 8);
    v += __shfl_xor_sync(0xffffffffu, v, 4, 8);

    if (valid && j == 0) out[b] = v + __ldg(b_fc);
}

extern "C" void kernel_launch(void* const* d_in, const int* in_sizes, int n_in,
                              void* d_out, int out_size)
{
    const float* x    = (const float*)d_in[0];
    const float* W_ih = (const float*)d_in[1];
    const float* W_hh = (const float*)d_in[2];
    const float* b_ih = (const float*)d_in[3];
    const float* b_hh = (const float*)d_in[4];
    const float* W_fc = (const float*)d_in[5];
    const float* b_fc = (const float*)d_in[6];
    float* out = (float*)d_out;

    const int B = in_sizes[0] / (T_SEQ * IDIM);     // 8192 here
    const int groups_per_block = 8;                 // 64 threads / 8 lanes
    const int grid = (B + groups_per_block - 1) / groups_per_block;

    lstm_fused_kernel<<<grid, 64>>>(x, W_ih, W_hh, b_ih, b_hh, W_fc, b_fc, out, B);
}

// round 11
// speedup vs baseline: 1.0578x; 1.0578x over previous
#include <cuda_runtime.h>
#include <cstdint>

// LSTM: B x T x I -> last hidden -> FC.  I=4, H=8, O=1, T=512.
// Round-11 = Round-4 skeleton with the recurrent projection moved to fp16
// HFMA2 (rt2) to cut the binding fma-pipe load (f32x2 fma is rt3 due to RF
// banking: 3 even + 3 odd distinct regs). Changes vs R4:
//   * recurrent 16x fma2 (48 fma-cyc) -> 18x HFMA2/HMUL2/HADD2 (36 fma-cyc)
//   * h broadcast as pre-duplicated f16x2: 1 cvt makes (h,h); 8x 32-bit shfl
//     feed HFMA2 directly (8 dup2 movs gone)
//   * gate activations via tanh.approx.f16x2 (R10 block, measured 1.3e-4)
// Input projection, c, tanh(c), h stay f32. 8 lanes/batch, 2048 warps,
// folded 0.5 sigmoid scales, 4-deep x prefetch.

#define T_SEQ 512
#define IDIM  4
#define HDIM  8

typedef unsigned long long u64;

__device__ __forceinline__ u64 pack2(float a, float b) {
    u64 r; asm("mov.b64 %0,{%1,%2};" : "=l"(r) : "f"(a), "f"(b)); return r;
}
__device__ __forceinline__ u64 dup2(float a) {
    u64 r; asm("mov.b64 %0,{%1,%1};" : "=l"(r) : "f"(a)); return r;
}
__device__ __forceinline__ float2 unpack2(u64 v) {
    float2 r; asm("mov.b64 {%0,%1},%2;" : "=f"(r.x), "=f"(r.y) : "l"(v)); return r;
}
__device__ __forceinline__ u64 fma2(u64 a, u64 b, u64 c) {
    u64 d; asm("fma.rn.f32x2 %0,%1,%2,%3;" : "=l"(d) : "l"(a), "l"(b), "l"(c)); return d;
}
__device__ __forceinline__ float tanh_fast(float x) {
    float y; asm("tanh.approx.f32 %0,%1;" : "=f"(y) : "f"(x)); return y;
}
// f16x2 helpers: first cvt source -> HI half (convention validated in R10)
__device__ __forceinline__ uint32_t cvt_f16x2(float hi, float lo) {
    uint32_t r; asm("cvt.rn.f16x2.f32 %0, %1, %2;" : "=r"(r) : "f"(hi), "f"(lo)); return r;
}
__device__ __forceinline__ uint32_t hfma2(uint32_t a, uint32_t b, uint32_t c) {
    uint32_t d; asm("fma.rn.f16x2 %0,%1,%2,%3;" : "=r"(d) : "r"(a), "r"(b), "r"(c)); return d;
}
__device__ __forceinline__ uint32_t hmul2(uint32_t a, uint32_t b) {
    uint32_t d; asm("mul.rn.f16x2 %0,%1,%2;" : "=r"(d) : "r"(a), "r"(b)); return d;
}
__device__ __forceinline__ uint32_t hadd2(uint32_t a, uint32_t b) {
    uint32_t d; asm("add.rn.f16x2 %0,%1,%2;" : "=r"(d) : "r"(a), "r"(b)); return d;
}
__device__ __forceinline__ uint32_t htanh2(uint32_t a) {
    uint32_t d; asm("tanh.approx.f16x2 %0,%1;" : "=r"(d) : "r"(a)); return d;
}
__device__ __forceinline__ float2 cvt_f32x2(uint32_t p) {   // (lo, hi)
    float lo, hi;
    asm("{ .reg .f16 l, h; mov.b32 {l, h}, %2;"
        "  cvt.f32.f16 %0, l; cvt.f32.f16 %1, h; }"
        : "=f"(lo), "=f"(hi) : "r"(p));
    return make_float2(lo, hi);
}

__global__ __launch_bounds__(64)
void lstm_fused_kernel(const float* __restrict__ x,
                       const float* __restrict__ W_ih,
                       const float* __restrict__ W_hh,
                       const float* __restrict__ b_ih,
                       const float* __restrict__ b_hh,
                       const float* __restrict__ W_fc,
                       const float* __restrict__ b_fc,
                       float* __restrict__ out,
                       int B)
{
    const int tid = threadIdx.x;
    const int j   = tid & 7;                        // hidden unit owned by this lane
    int b = blockIdx.x * 8 + (tid >> 3);            // batch element
    const bool valid = (b < B);
    if (b >= B) b = B - 1;                          // clamp: keep warp converged

    // ---- weights ----
    // f32 input projection, gate-pair packed (lo=i|g, hi=f|o); sigmoid rows
    // pre-scaled by 0.5 so sigmoid(z) = 0.5*tanh(acc)+0.5.
    u64 wih01[IDIM], wih23[IDIM], bias01, bias23;
    // fp16 recurrent weights, gate-pair half2 (lo=i|g, hi=f|o)
    uint32_t whhIF[HDIM], whhGO[HDIM];
    {
        const int r0 = 0 * HDIM + j;   // i
        const int r1 = 1 * HDIM + j;   // f
        const int r2 = 2 * HDIM + j;   // g
        const int r3 = 3 * HDIM + j;   // o
#pragma unroll
        for (int m = 0; m < IDIM; ++m) {
            wih01[m] = pack2(0.5f * W_ih[r0 * IDIM + m], 0.5f * W_ih[r1 * IDIM + m]);
            wih23[m] = pack2(        W_ih[r2 * IDIM + m], 0.5f * W_ih[r3 * IDIM + m]);
        }
#pragma unroll
        for (int k = 0; k < HDIM; ++k) {
            whhIF[k] = cvt_f16x2(0.5f * W_hh[r1 * HDIM + k],   // hi = f
                                 0.5f * W_hh[r0 * HDIM + k]);  // lo = i
            whhGO[k] = cvt_f16x2(0.5f * W_hh[r3 * HDIM + k],   // hi = o
                                         W_hh[r2 * HDIM + k]); // lo = g
        }
        bias01 = pack2(0.5f * (b_ih[r0] + b_hh[r0]), 0.5f * (b_ih[r1] + b_hh[r1]));
        bias23 = pack2(        b_ih[r2] + b_hh[r2],  0.5f * (b_ih[r3] + b_hh[r3]));
    }

    // half2 activation constants
    const uint32_t K_05_05 = 0x38003800u;   // (hi=0.5, lo=0.5)
    const uint32_t K_MULGO = 0x38003C00u;   // hi=0.5 (o), lo=1.0 (g)
    const uint32_t K_ADDGO = 0x38000000u;   // hi=0.5 (o), lo=0.0 (g)

    const float4* __restrict__ xp =
        reinterpret_cast<const float4*>(x) + (size_t)b * T_SEQ;

    float h = 0.0f, c = 0.0f;
    uint32_t hd = 0;                        // (h,h) in f16x2 for broadcast

    // rolling 4-step prefetch buffer (covers DRAM miss latency, MLP=4)
    float4 buf0 = xp[0], buf1 = xp[1], buf2 = xp[2], buf3 = xp[3];

#pragma unroll 1
    for (int t0 = 0; t0 < T_SEQ; t0 += 4) {
        const int tn = (t0 + 4) & (T_SEQ - 1);      // wraps on last iter (harmless)
        const float4 n0 = xp[tn + 0];
        const float4 n1 = xp[tn + 1];
        const float4 n2 = xp[tn + 2];
        const float4 n3 = xp[tn + 3];

        const float4 bufs[4] = {buf0, buf1, buf2, buf3};
#pragma unroll
        for (int u = 0; u < 4; ++u) {
            const float4 xc = bufs[u];

            // ---- f32 input projection + bias (h-independent, off-chain) ----
            const u64 d0 = dup2(xc.x), d1 = dup2(xc.y), d2 = dup2(xc.z), d3 = dup2(xc.w);
            u64 p01 = fma2(wih01[0], d0, bias01);
            u64 p23 = fma2(wih23[0], d0, bias23);
            p01 = fma2(wih01[1], d1, p01);  p23 = fma2(wih23[1], d1, p23);
            p01 = fma2(wih01[2], d2, p01);  p23 = fma2(wih23[2], d2, p23);
            p01 = fma2(wih01[3], d3, p01);  p23 = fma2(wih23[3], d3, p23);

            // convert partials to f16x2 (off-chain: before h arrives)
            const float2 t01 = unpack2(p01);         // (zi', zf') partial
            const float2 t23 = unpack2(p23);         // (zg,  zo') partial
            const uint32_t zif0 = cvt_f16x2(t01.y, t01.x);   // hi=f, lo=i
            const uint32_t zgo0 = cvt_f16x2(t23.y, t23.x);   // hi=o, lo=g

            // ---- broadcast duplicated-h f16x2 within the 8-lane group ----
            const uint32_t h0 = __shfl_sync(0xffffffffu, hd, 0, 8);
            const uint32_t h1 = __shfl_sync(0xffffffffu, hd, 1, 8);
            const uint32_t h2 = __shfl_sync(0xffffffffu, hd, 2, 8);
            const uint32_t h3 = __shfl_sync(0xffffffffu, hd, 3, 8);
            const uint32_t h4 = __shfl_sync(0xffffffffu, hd, 4, 8);
            const uint32_t h5 = __shfl_sync(0xffffffffu, hd, 5, 8);
            const uint32_t h6 = __shfl_sync(0xffffffffu, hd, 6, 8);
            const uint32_t h7 = __shfl_sync(0xffffffffu, hd, 7, 8);

            // ---- fp16 recurrent projection, even/odd split ----
            uint32_t pif = hfma2(whhIF[0], h0, zif0);
            uint32_t pgo = hfma2(whhGO[0], h0, zgo0);
            uint32_t qif = hmul2(whhIF[4], h4);
            uint32_t qgo = hmul2(whhGO[4], h4);
            pif = hfma2(whhIF[1], h1, pif);  pgo = hfma2(whhGO[1], h1, pgo);
            qif = hfma2(whhIF[5], h5, qif);  qgo = hfma2(whhGO[5], h5, qgo);
            pif = hfma2(whhIF[2], h2, pif);  pgo = hfma2(whhGO[2], h2, pgo);
            qif = hfma2(whhIF[6], h6, qif);  qgo = hfma2(whhGO[6], h6, qgo);
            pif = hfma2(whhIF[3], h3, pif);  pgo = hfma2(whhGO[3], h3, pgo);
            qif = hfma2(whhIF[7], h7, qif);  qgo = hfma2(whhGO[7], h7, qgo);
            const uint32_t aif = hadd2(pif, qif);    // (zi/2, zf/2)
            const uint32_t ago = hadd2(pgo, qgo);    // (zg,   zo/2)

            // ---- gate activations: 2x packed f16x2 tanh ----
            const uint32_t tif = htanh2(aif);
            const uint32_t tgo = htanh2(ago);
            const uint32_t sif = hfma2(tif, K_05_05, K_05_05);   // (i, f)
            const uint32_t sgo = hfma2(tgo, K_MULGO, K_ADDGO);   // (g, o)
            const float2 gif = cvt_f32x2(sif);       // (i, f)
            const float2 ggo = cvt_f32x2(sgo);       // (g, o)

            // ---- f32 state update ----
            c = fmaf(gif.y, c, gif.x * ggo.x);       // f*c + i*g
            h = ggo.y * tanh_fast(c);                // o * tanh(c)
            hd = cvt_f16x2(h, h);                    // duplicated for broadcast
        }

        buf0 = n0; buf1 = n1; buf2 = n2; buf3 = n3;
    }

    // ---- FC head: out[b] = sum_j h_j * W_fc[j] + b_fc ----
    float v = h * __ldg(W_fc + j);
    v += __shfl_xor_sync(0xffffffffu, v, 1, 8);
    v += __shfl_xor_sync(0xffffffffu, v, 2, 8);
    v += __shfl_xor_sync(0xffffffffu, v, 4, 8);

    if (valid && j == 0) out[b] = v + __ldg(b_fc);
}

extern "C" void kernel_launch(void* const* d_in, const int* in_sizes, int n_in,
                              void* d_out, int out_size)
{
    const float* x    = (const float*)d_in[0];
    const float* W_ih = (const float*)d_in[1];
    const float* W_hh = (const float*)d_in[2];
    const float* b_ih = (const float*)d_in[3];
    const float* b_hh = (const float*)d_in[4];
    const float* W_fc = (const float*)d_in[5];
    const float* b_fc = (const float*)d_in[6];
    float* out = (float*)d_out;

    const int B = in_sizes[0] / (T_SEQ * IDIM);     // 8192 here
    const int groups_per_block = 8;                 // 64 threads / 8 lanes
    const int grid = (B + groups_per_block - 1) / groups_per_block;

    lstm_fused_kernel<<<grid, 64>>>(x, W_ih, W_hh, b_ih, b_hh, W_fc, b_fc, out, B);
}

// round 12
// speedup vs baseline: 1.3064x; 1.2350x over previous
#include <cuda_runtime.h>
#include <cstdint>

// LSTM: B x T x I -> last hidden -> FC.  I=4, H=8, O=1, T=512.
// Round-12: tensor-core recurrence. One warp owns 16 batch rows; per step the
// four gate pre-activations come from 4x mma.sync.m16n8k16 (f16 in, f32 acc):
//     A[16 x 16] = [ h (k=0..7) | x (k=8..11) | 1 (k=12) | 0 ]
//     B[16 x 8]  = [ W_hh^T ; W_ih^T ; bias ; 0 ]   (one per gate)
// The m16n8 D fragment layout equals the m16k8 A fragment layout, so gates ->
// activations -> h repack into next step's A with ZERO cross-lane traffic
// (the shfl+MUFU serial chain that capped every SIMT variant at ~100us dies).
// Gate activations: packed tanh.approx.f16x2 (10 MUFU/warp-step for 16
// batches). c kept in f32. x via 8-step ping-pong register prefetch.

#define T_SEQ 512
#define IDIM  4
#define HDIM  8

__device__ __forceinline__ uint32_t cvt_f16x2(float hi, float lo) {
    uint32_t r; asm("cvt.rn.f16x2.f32 %0, %1, %2;" : "=r"(r) : "f"(hi), "f"(lo)); return r;
}
__device__ __forceinline__ uint32_t htanh2(uint32_t a) {
    uint32_t d; asm("tanh.approx.f16x2 %0,%1;" : "=r"(d) : "r"(a)); return d;
}
__device__ __forceinline__ uint32_t hfma2(uint32_t a, uint32_t b, uint32_t c) {
    uint32_t d; asm("fma.rn.f16x2 %0,%1,%2,%3;" : "=r"(d) : "r"(a), "r"(b), "r"(c)); return d;
}
__device__ __forceinline__ uint32_t hmul2(uint32_t a, uint32_t b) {
    uint32_t d; asm("mul.rn.f16x2 %0,%1,%2;" : "=r"(d) : "r"(a), "r"(b)); return d;
}
__device__ __forceinline__ float2 cvt_f32x2(uint32_t p) {   // (lo, hi)
    float lo, hi;
    asm("{ .reg .f16 l, h; mov.b32 {l, h}, %2;"
        "  cvt.f32.f16 %0, l; cvt.f32.f16 %1, h; }"
        : "=f"(lo), "=f"(hi) : "r"(p));
    return make_float2(lo, hi);
}
__device__ __forceinline__ void mma16816(float d[4],
                                         uint32_t a0, uint32_t a1, uint32_t a2, uint32_t a3,
                                         uint32_t b0, uint32_t b1)
{
    const float z = 0.0f;
    asm("mma.sync.aligned.m16n8k16.row.col.f32.f16.f16.f32 "
        "{%0,%1,%2,%3}, {%4,%5,%6,%7}, {%8,%9}, {%10,%11,%12,%13};"
        : "=f"(d[0]), "=f"(d[1]), "=f"(d[2]), "=f"(d[3])
        : "r"(a0), "r"(a1), "r"(a2), "r"(a3), "r"(b0), "r"(b1),
          "f"(z), "f"(z), "f"(z), "f"(z));
}

struct State {
    float c00, c01, c10, c11;    // c at (r0,u0),(r0,u1),(r1,u0),(r1,u1)
    uint32_t a0, a1;             // h as next-step A frag (f16x2: lo=u0, hi=u1)
};

// one timestep: 4 MMAs + packed activations; no cross-lane ops.
__device__ __forceinline__ void lstm_step(const uint32_t bf[4][2],
                                          uint32_t a2, uint32_t a3, State& S)
{
    const uint32_t K05 = 0x38003800u;    // (0.5, 0.5) half2

    float di[4], df[4], dg[4], dw[4];
    mma16816(di, S.a0, S.a1, a2, a3, bf[0][0], bf[0][1]);   // i (z/2)
    mma16816(df, S.a0, S.a1, a2, a3, bf[1][0], bf[1][1]);   // f (z/2)
    mma16816(dg, S.a0, S.a1, a2, a3, bf[2][0], bf[2][1]);   // g (z)
    mma16816(dw, S.a0, S.a1, a2, a3, bf[3][0], bf[3][1]);   // o (z/2)

    // pack (lo=u0, hi=u1) per row-half, tanh, sigmoid-affine
    const uint32_t ti0 = htanh2(cvt_f16x2(di[1], di[0]));
    const uint32_t ti1 = htanh2(cvt_f16x2(di[3], di[2]));
    const uint32_t tf0 = htanh2(cvt_f16x2(df[1], df[0]));
    const uint32_t tf1 = htanh2(cvt_f16x2(df[3], df[2]));
    const uint32_t tg0 = htanh2(cvt_f16x2(dg[1], dg[0]));   // g = tanh(z)
    const uint32_t tg1 = htanh2(cvt_f16x2(dg[3], dg[2]));
    const uint32_t to0 = htanh2(cvt_f16x2(dw[1], dw[0]));
    const uint32_t to1 = htanh2(cvt_f16x2(dw[3], dw[2]));

    const uint32_t si0 = hfma2(ti0, K05, K05);   // i = 0.5 t + 0.5
    const uint32_t si1 = hfma2(ti1, K05, K05);
    const uint32_t sf0 = hfma2(tf0, K05, K05);
    const uint32_t sf1 = hfma2(tf1, K05, K05);
    const uint32_t so0 = hfma2(to0, K05, K05);
    const uint32_t so1 = hfma2(to1, K05, K05);

    // unpack i,f,g to f32 for the c update
    const float2 i0 = cvt_f32x2(si0), i1 = cvt_f32x2(si1);
    const float2 f0 = cvt_f32x2(sf0), f1 = cvt_f32x2(sf1);
    const float2 g0 = cvt_f32x2(tg0), g1 = cvt_f32x2(tg1);

    S.c00 = fmaf(f0.x, S.c00, i0.x * g0.x);
    S.c01 = fmaf(f0.y, S.c01, i0.y * g0.y);
    S.c10 = fmaf(f1.x, S.c10, i1.x * g1.x);
    S.c11 = fmaf(f1.y, S.c11, i1.y * g1.y);

    // h = o * tanh(c): result IS next step's A fragment (k=0..7 half)
    const uint32_t tc0 = htanh2(cvt_f16x2(S.c01, S.c00));
    const uint32_t tc1 = htanh2(cvt_f16x2(S.c11, S.c10));
    S.a0 = hmul2(so0, tc0);
    S.a1 = hmul2(so1, tc1);
}

__device__ __forceinline__ void load8(const float* xr0, const float* xr1, int t0,
                                      uint32_t (&xa)[8], uint32_t (&xb)[8], bool doload)
{
    if (doload) {
#pragma unroll
        for (int i = 0; i < 8; ++i) {
            const int t = (t0 + i) & (T_SEQ - 1);
            const float2 p0 = *reinterpret_cast<const float2*>(xr0 + (size_t)t * IDIM);
            const float2 p1 = *reinterpret_cast<const float2*>(xr1 + (size_t)t * IDIM);
            xa[i] = cvt_f16x2(p0.y, p0.x);
            xb[i] = cvt_f16x2(p1.y, p1.x);
        }
    }
}

__global__ __launch_bounds__(32)
void lstm_mma_kernel(const float* __restrict__ x,
                     const float* __restrict__ W_ih,
                     const float* __restrict__ W_hh,
                     const float* __restrict__ b_ih,
                     const float* __restrict__ b_hh,
                     const float* __restrict__ W_fc,
                     const float* __restrict__ b_fc,
                     float* __restrict__ out,
                     int B)
{
    const int lane = threadIdx.x & 31;
    const int grp  = lane >> 2;                     // 0..7: row group / B n-index
    const int q    = lane & 3;                      // k-pair selector

    const int base = blockIdx.x * 16;               // this warp's 16 batch rows
    const int r0 = base + grp;
    const int r1 = base + grp + 8;
    const bool v0 = (r0 < B), v1 = (r1 < B);
    const int r0c = v0 ? r0 : (B - 1);
    const int r1c = v1 ? r1 : (B - 1);

    // ---- B fragments (col-major k16n8) per gate; sigmoid rows scaled 0.5 ----
    // B[k][n]: k<8: s*W_hh[row,k]; k=8..11: s*W_ih[row,k-8]; k=12: s*bias; else 0
    uint32_t bf[4][2];
#pragma unroll
    for (int gt = 0; gt < 4; ++gt) {
        const float s = (gt == 2) ? 1.0f : 0.5f;
        const int row = gt * HDIM + grp;            // n = grp
        float bv[4];                                 // k = 2q, 2q+1, 2q+8, 2q+9
#pragma unroll
        for (int half = 0; half < 2; ++half) {
#pragma unroll
            for (int e = 0; e < 2; ++e) {
                const int k = 2 * q + e + 8 * half;
                float v;
                if (k < 8)        v = s * W_hh[row * HDIM + k];
                else if (k < 12)  v = s * W_ih[row * IDIM + (k - 8)];
                else if (k == 12) v = s * (b_ih[row] + b_hh[row]);
                else              v = 0.0f;
                bv[2 * half + e] = v;
            }
        }
        bf[gt][0] = cvt_f16x2(bv[1], bv[0]);
        bf[gt][1] = cvt_f16x2(bv[3], bv[2]);
    }

    // ---- x / constant columns for A k=8..15 ----
    // q=0: (x0,x1); q=1: (x2,x3); q=2: (1,0) [bias column]; q=3: (0,0)
    const bool xlane = (q < 2);
    const uint32_t cA = (q == 2) ? 0x00003C00u : 0u;  // lo=1.0h, hi=0
    const float* xr0 = x + (size_t)r0c * T_SEQ * IDIM + 2 * q;
    const float* xr1 = x + (size_t)r1c * T_SEQ * IDIM + 2 * q;

    uint32_t bufAa[8], bufAb[8], bufBa[8], bufBb[8];
#pragma unroll
    for (int i = 0; i < 8; ++i) { bufAa[i] = cA; bufAb[i] = cA; bufBa[i] = cA; bufBb[i] = cA; }
    load8(xr0, xr1, 0, bufAa, bufAb, xlane);

    State S;
    S.c00 = S.c01 = S.c10 = S.c11 = 0.0f;
    S.a0 = 0u; S.a1 = 0u;                            // h = 0

#pragma unroll 1
    for (int t0 = 0; t0 < T_SEQ; t0 += 16) {
        load8(xr0, xr1, t0 + 8, bufBa, bufBb, xlane);
#pragma unroll
        for (int i = 0; i < 8; ++i) lstm_step(bf, bufAa[i], bufAb[i], S);

        load8(xr0, xr1, (t0 + 16) & (T_SEQ - 1), bufAa, bufAb, xlane);
#pragma unroll
        for (int i = 0; i < 8; ++i) lstm_step(bf, bufBa[i], bufBb[i], S);
    }

    // ---- FC head: out[b] = sum_u h[b,u] * W_fc[u] + b_fc ----
    // thread holds h(r0,u0),(r0,u1) in a0 and (r1,*) in a1, units u=2q,2q+1
    const float w0 = __ldg(W_fc + 2 * q);
    const float w1 = __ldg(W_fc + 2 * q + 1);
    const float2 h0 = cvt_f32x2(S.a0);
    const float2 h1 = cvt_f32x2(S.a1);
    float v0r = h0.x * w0 + h0.y * w1;
    float v1r = h1.x * w0 + h1.y * w1;
    v0r += __shfl_xor_sync(0xffffffffu, v0r, 1, 4);
    v0r += __shfl_xor_sync(0xffffffffu, v0r, 2, 4);
    v1r += __shfl_xor_sync(0xffffffffu, v1r, 1, 4);
    v1r += __shfl_xor_sync(0xffffffffu, v1r, 2, 4);

    if (q == 0) {
        const float bfc = __ldg(b_fc);
        if (v0) out[r0] = v0r + bfc;
        if (v1) out[r1] = v1r + bfc;
    }
}

extern "C" void kernel_launch(void* const* d_in, const int* in_sizes, int n_in,
                              void* d_out, int out_size)
{
    const float* x    = (const float*)d_in[0];
    const float* W_ih = (const float*)d_in[1];
    const float* W_hh = (const float*)d_in[2];
    const float* b_ih = (const float*)d_in[3];
    const float* b_hh = (const float*)d_in[4];
    const float* W_fc = (const float*)d_in[5];
    const float* b_fc = (const float*)d_in[6];
    float* out = (float*)d_out;

    const int B = in_sizes[0] / (T_SEQ * IDIM);     // 8192 here
    const int grid = (B + 15) / 16;                 // one 32-thread warp per 16 batches

    lstm_mma_kernel<<<grid, 32>>>(x, W_ih, W_hh, b_ih, b_hh, W_fc, b_fc, out, B);
}

// round 13
// speedup vs baseline: 1.3142x; 1.0060x over previous
#include <cuda_runtime.h>
#include <cstdint>

// LSTM: B x T x I -> last hidden -> FC.  I=4, H=8, O=1, T=512.
// Round-13: chain surgery on the R12 tensor-core recurrence (chain-bound:
// wall = 512 x step-chain). Changes:
//   * m16n8k16 -> m16n8k8: input projection + bias precomputed OFF-CHAIN one
//     step ahead and fed through the MMA C operand; only h@W_hh^T stays on
//     the serial chain.
//   * f16 D accumulators: m16n8k8 f16-D fragment layout == A fragment layout,
//     so D -> tanh -> h -> next A with ZERO repacking (8 pack-cvts off chain).
//   * c stays f32 (R12-validated precision recipe).
// One warp = 16 batch rows, 512 warps, everything in registers.

#define T_SEQ 512
#define IDIM  4
#define HDIM  8

__device__ __forceinline__ uint32_t cvt_f16x2(float hi, float lo) {
    uint32_t r; asm("cvt.rn.f16x2.f32 %0, %1, %2;" : "=r"(r) : "f"(hi), "f"(lo)); return r;
}
__device__ __forceinline__ uint32_t htanh2(uint32_t a) {
    uint32_t d; asm("tanh.approx.f16x2 %0,%1;" : "=r"(d) : "r"(a)); return d;
}
__device__ __forceinline__ uint32_t hfma2(uint32_t a, uint32_t b, uint32_t c) {
    uint32_t d; asm("fma.rn.f16x2 %0,%1,%2,%3;" : "=r"(d) : "r"(a), "r"(b), "r"(c)); return d;
}
__device__ __forceinline__ uint32_t hmul2(uint32_t a, uint32_t b) {
    uint32_t d; asm("mul.rn.f16x2 %0,%1,%2;" : "=r"(d) : "r"(a), "r"(b)); return d;
}
__device__ __forceinline__ float2 cvt_f32x2(uint32_t p) {   // (lo, hi)
    float lo, hi;
    asm("{ .reg .f16 l, h; mov.b32 {l, h}, %2;"
        "  cvt.f32.f16 %0, l; cvt.f32.f16 %1, h; }"
        : "=f"(lo), "=f"(hi) : "r"(p));
    return make_float2(lo, hi);
}
// m16n8k8, f16 in / f16 out, C operand carries the precomputed input proj.
__device__ __forceinline__ void mma16808(uint32_t d[2],
                                         uint32_t a0, uint32_t a1, uint32_t b,
                                         uint32_t c0, uint32_t c1)
{
    asm("mma.sync.aligned.m16n8k8.row.col.f16.f16.f16.f16 "
        "{%0,%1}, {%2,%3}, {%4}, {%5,%6};"
        : "=r"(d[0]), "=r"(d[1])
        : "r"(a0), "r"(a1), "r"(b), "r"(c0), "r"(c1));
}

__global__ __launch_bounds__(32)
void lstm_mma_kernel(const float* __restrict__ x,
                     const float* __restrict__ W_ih,
                     const float* __restrict__ W_hh,
                     const float* __restrict__ b_ih,
                     const float* __restrict__ b_hh,
                     const float* __restrict__ W_fc,
                     const float* __restrict__ b_fc,
                     float* __restrict__ out,
                     int B)
{
    const int lane = threadIdx.x & 31;
    const int grp  = lane >> 2;                     // row group / B n-index
    const int q    = lane & 3;                      // col-pair selector

    const int base = blockIdx.x * 16;
    const int r0 = base + grp;
    const int r1 = base + grp + 8;
    const bool v0 = (r0 < B), v1 = (r1 < B);
    const int r0c = v0 ? r0 : (B - 1);
    const int r1c = v1 ? r1 : (B - 1);

    // ---- B fragments (k8 x n8, col-major), one per gate; sigmoid rows x0.5 ----
    uint32_t breg[4];
#pragma unroll
    for (int gt = 0; gt < 4; ++gt) {
        const float s = (gt == 2) ? 1.0f : 0.5f;
        const int row = gt * HDIM + grp;            // n = grp
        breg[gt] = cvt_f16x2(s * W_hh[row * HDIM + 2 * q + 1],
                             s * W_hh[row * HDIM + 2 * q]);
    }

    // ---- W_ih / bias in unit-pair f16x2 (lo = unit 2q, hi = unit 2q+1) ----
    uint32_t wih[4][IDIM], bias[4];
    {
        const int u0 = 2 * q, u1 = 2 * q + 1;
#pragma unroll
        for (int gt = 0; gt < 4; ++gt) {
            const float s = (gt == 2) ? 1.0f : 0.5f;
            const int ra = gt * HDIM + u0, rb = gt * HDIM + u1;
#pragma unroll
            for (int k = 0; k < IDIM; ++k)
                wih[gt][k] = cvt_f16x2(s * W_ih[rb * IDIM + k],
                                       s * W_ih[ra * IDIM + k]);
            bias[gt] = cvt_f16x2(s * (b_ih[rb] + b_hh[rb]),
                                 s * (b_ih[ra] + b_hh[ra]));
        }
    }

    const float4* __restrict__ xp0 =
        reinterpret_cast<const float4*>(x) + (size_t)r0c * T_SEQ;
    const float4* __restrict__ xp1 =
        reinterpret_cast<const float4*>(x) + (size_t)r1c * T_SEQ;

    const uint32_t K05 = 0x38003800u;               // (0.5, 0.5) half2

    // state
    uint32_t a0 = 0u, a1 = 0u;                      // h as A fragment (f16x2)
    float c00 = 0.f, c01 = 0.f, c10 = 0.f, c11 = 0.f;

    // ---- IP(t) = x_t @ W_ih^T + bias, in C-fragment layout (f16x2 x 2 rows) ----
    auto ip_build = [&](const float4 x0, const float4 x1, uint32_t (&ip)[4][2]) {
        uint32_t d00 = cvt_f16x2(x0.x, x0.x), d01 = cvt_f16x2(x0.y, x0.y);
        uint32_t d02 = cvt_f16x2(x0.z, x0.z), d03 = cvt_f16x2(x0.w, x0.w);
        uint32_t d10 = cvt_f16x2(x1.x, x1.x), d11 = cvt_f16x2(x1.y, x1.y);
        uint32_t d12 = cvt_f16x2(x1.z, x1.z), d13 = cvt_f16x2(x1.w, x1.w);
#pragma unroll
        for (int gt = 0; gt < 4; ++gt) {
            uint32_t p = hfma2(d00, wih[gt][0], bias[gt]);
            p = hfma2(d01, wih[gt][1], p);
            p = hfma2(d02, wih[gt][2], p);
            ip[gt][0] = hfma2(d03, wih[gt][3], p);
            uint32_t r = hfma2(d10, wih[gt][0], bias[gt]);
            r = hfma2(d11, wih[gt][1], r);
            r = hfma2(d12, wih[gt][2], r);
            ip[gt][1] = hfma2(d13, wih[gt][3], r);
        }
    };

    // rolling 4-step x prefetch
    float4 b0[4], b1[4];
#pragma unroll
    for (int i = 0; i < 4; ++i) { b0[i] = xp0[i]; b1[i] = xp1[i]; }

    uint32_t ip[4][2];
    ip_build(b0[0], b1[0], ip);                     // IP(0)

#pragma unroll 1
    for (int t0 = 0; t0 < T_SEQ; t0 += 4) {
        const int tn = (t0 + 4) & (T_SEQ - 1);
        float4 n0[4], n1[4];
#pragma unroll
        for (int i = 0; i < 4; ++i) { n0[i] = xp0[tn + i]; n1[i] = xp1[tn + i]; }

#pragma unroll
        for (int u = 0; u < 4; ++u) {
            // build IP(t+1) (off-chain; overlaps the MMA/tanh chain below)
            uint32_t ipn[4][2];
            const float4 xa = (u < 3) ? b0[u + 1] : n0[0];
            const float4 xb = (u < 3) ? b1[u + 1] : n1[0];
            ip_build(xa, xb, ipn);

            // ---- 4 gate MMAs (k8, f16 D), C = IP(t) ----
            uint32_t dI[2], dF[2], dG[2], dO[2];
            mma16808(dI, a0, a1, breg[0], ip[0][0], ip[0][1]);
            mma16808(dF, a0, a1, breg[1], ip[1][0], ip[1][1]);
            mma16808(dG, a0, a1, breg[2], ip[2][0], ip[2][1]);
            mma16808(dO, a0, a1, breg[3], ip[3][0], ip[3][1]);

            // ---- activations (D frag == A frag layout: no repacking) ----
            const uint32_t sI0 = hfma2(htanh2(dI[0]), K05, K05);
            const uint32_t sI1 = hfma2(htanh2(dI[1]), K05, K05);
            const uint32_t sF0 = hfma2(htanh2(dF[0]), K05, K05);
            const uint32_t sF1 = hfma2(htanh2(dF[1]), K05, K05);
            const uint32_t tG0 = htanh2(dG[0]);
            const uint32_t tG1 = htanh2(dG[1]);
            const uint32_t sO0 = hfma2(htanh2(dO[0]), K05, K05);
            const uint32_t sO1 = hfma2(htanh2(dO[1]), K05, K05);

            // ---- c update in f32 ----
            const float2 iA = cvt_f32x2(sI0), iB = cvt_f32x2(sI1);
            const float2 fA = cvt_f32x2(sF0), fB = cvt_f32x2(sF1);
            const float2 gA = cvt_f32x2(tG0), gB = cvt_f32x2(tG1);
            c00 = fmaf(fA.x, c00, iA.x * gA.x);
            c01 = fmaf(fA.y, c01, iA.y * gA.y);
            c10 = fmaf(fB.x, c10, iB.x * gB.x);
            c11 = fmaf(fB.y, c11, iB.y * gB.y);

            // ---- h = o * tanh(c): lands directly as next A fragment ----
            const uint32_t tc0 = htanh2(cvt_f16x2(c01, c00));
            const uint32_t tc1 = htanh2(cvt_f16x2(c11, c10));
            a0 = hmul2(sO0, tc0);
            a1 = hmul2(sO1, tc1);

            // rotate IP
#pragma unroll
            for (int gt = 0; gt < 4; ++gt) { ip[gt][0] = ipn[gt][0]; ip[gt][1] = ipn[gt][1]; }
        }

#pragma unroll
        for (int i = 0; i < 4; ++i) { b0[i] = n0[i]; b1[i] = n1[i]; }
    }

    // ---- FC head: out[b] = sum_u h[b,u] * W_fc[u] + b_fc ----
    const float w0 = __ldg(W_fc + 2 * q);
    const float w1 = __ldg(W_fc + 2 * q + 1);
    const float2 h0 = cvt_f32x2(a0);
    const float2 h1 = cvt_f32x2(a1);
    float v0r = h0.x * w0 + h0.y * w1;
    float v1r = h1.x * w0 + h1.y * w1;
    v0r += __shfl_xor_sync(0xffffffffu, v0r, 1, 4);
    v0r += __shfl_xor_sync(0xffffffffu, v0r, 2, 4);
    v1r += __shfl_xor_sync(0xffffffffu, v1r, 1, 4);
    v1r += __shfl_xor_sync(0xffffffffu, v1r, 2, 4);

    if (q == 0) {
        const float bfc = __ldg(b_fc);
        if (v0) out[r0] = v0r + bfc;
        if (v1) out[r1] = v1r + bfc;
    }
}

extern "C" void kernel_launch(void* const* d_in, const int* in_sizes, int n_in,
                              void* d_out, int out_size)
{
    const float* x    = (const float*)d_in[0];
    const float* W_ih = (const float*)d_in[1];
    const float* W_hh = (const float*)d_in[2];
    const float* b_ih = (const float*)d_in[3];
    const float* b_hh = (const float*)d_in[4];
    const float* W_fc = (const float*)d_in[5];
    const float* b_fc = (const float*)d_in[6];
    float* out = (float*)d_out;

    const int B = in_sizes[0] / (T_SEQ * IDIM);     // 8192 here
    const int grid = (B + 15) / 16;                 // one warp per 16 batches

    lstm_mma_kernel<<<grid, 32>>>(x, W_ih, W_hh, b_ih, b_hh, W_fc, b_fc, out, B);
}

// round 14
// speedup vs baseline: 1.6126x; 1.2270x over previous
#include <cuda_runtime.h>
#include <cstdint>

// LSTM: B x T x I -> last hidden -> FC.  I=4, H=8, O=1, T=512.
// Round-14: discriminating experiment on the R13 tensor-core recurrence.
// Only 8 batch rows per warp (row-half 0 of the m16n8k8 fragments) ->
// 1024 warps (1.73/SMSP) and HALF the per-warp throughput load per step
// (5 htanh2, 2 FFMA c-update, half the IP build) with an IDENTICAL serial
// chain. If wall drops -> per-warp throughput-bound (more warps = faster).
// If wall stays 86us -> chain-bound on HMMA latency (next: SIMT quad ladder).
// Row-half 1 of A/C carries duplicated values; D[1] is ignored.

#define T_SEQ 512
#define IDIM  4
#define HDIM  8

__device__ __forceinline__ uint32_t cvt_f16x2(float hi, float lo) {
    uint32_t r; asm("cvt.rn.f16x2.f32 %0, %1, %2;" : "=r"(r) : "f"(hi), "f"(lo)); return r;
}
__device__ __forceinline__ uint32_t htanh2(uint32_t a) {
    uint32_t d; asm("tanh.approx.f16x2 %0,%1;" : "=r"(d) : "r"(a)); return d;
}
__device__ __forceinline__ uint32_t hfma2(uint32_t a, uint32_t b, uint32_t c) {
    uint32_t d; asm("fma.rn.f16x2 %0,%1,%2,%3;" : "=r"(d) : "r"(a), "r"(b), "r"(c)); return d;
}
__device__ __forceinline__ uint32_t hmul2(uint32_t a, uint32_t b) {
    uint32_t d; asm("mul.rn.f16x2 %0,%1,%2;" : "=r"(d) : "r"(a), "r"(b)); return d;
}
__device__ __forceinline__ float2 cvt_f32x2(uint32_t p) {   // (lo, hi)
    float lo, hi;
    asm("{ .reg .f16 l, h; mov.b32 {l, h}, %2;"
        "  cvt.f32.f16 %0, l; cvt.f32.f16 %1, h; }"
        : "=f"(lo), "=f"(hi) : "r"(p));
    return make_float2(lo, hi);
}
// m16n8k8, f16 in / f16 out; C carries the precomputed input projection.
__device__ __forceinline__ void mma16808(uint32_t d[2],
                                         uint32_t a0, uint32_t a1, uint32_t b,
                                         uint32_t c0, uint32_t c1)
{
    asm("mma.sync.aligned.m16n8k8.row.col.f16.f16.f16.f16 "
        "{%0,%1}, {%2,%3}, {%4}, {%5,%6};"
        : "=r"(d[0]), "=r"(d[1])
        : "r"(a0), "r"(a1), "r"(b), "r"(c0), "r"(c1));
}

__global__ __launch_bounds__(32)
void lstm_mma_kernel(const float* __restrict__ x,
                     const float* __restrict__ W_ih,
                     const float* __restrict__ W_hh,
                     const float* __restrict__ b_ih,
                     const float* __restrict__ b_hh,
                     const float* __restrict__ W_fc,
                     const float* __restrict__ b_fc,
                     float* __restrict__ out,
                     int B)
{
    const int lane = threadIdx.x & 31;
    const int grp  = lane >> 2;                     // row group / B n-index
    const int q    = lane & 3;                      // col-pair selector

    const int base = blockIdx.x * 8;                // 8 batch rows per warp
    const int r0 = base + grp;
    const bool v0 = (r0 < B);
    const int r0c = v0 ? r0 : (B - 1);

    // ---- B fragments (k8 x n8, col-major), one per gate; sigmoid rows x0.5 ----
    uint32_t breg[4];
#pragma unroll
    for (int gt = 0; gt < 4; ++gt) {
        const float s = (gt == 2) ? 1.0f : 0.5f;
        const int row = gt * HDIM + grp;            // n = grp
        breg[gt] = cvt_f16x2(s * W_hh[row * HDIM + 2 * q + 1],
                             s * W_hh[row * HDIM + 2 * q]);
    }

    // ---- W_ih / bias in unit-pair f16x2 (lo = unit 2q, hi = unit 2q+1) ----
    uint32_t wih[4][IDIM], bias[4];
    {
        const int u0 = 2 * q, u1 = 2 * q + 1;
#pragma unroll
        for (int gt = 0; gt < 4; ++gt) {
            const float s = (gt == 2) ? 1.0f : 0.5f;
            const int ra = gt * HDIM + u0, rb = gt * HDIM + u1;
#pragma unroll
            for (int k = 0; k < IDIM; ++k)
                wih[gt][k] = cvt_f16x2(s * W_ih[rb * IDIM + k],
                                       s * W_ih[ra * IDIM + k]);
            bias[gt] = cvt_f16x2(s * (b_ih[rb] + b_hh[rb]),
                                 s * (b_ih[ra] + b_hh[ra]));
        }
    }

    const float4* __restrict__ xp0 =
        reinterpret_cast<const float4*>(x) + (size_t)r0c * T_SEQ;

    const uint32_t K05 = 0x38003800u;               // (0.5, 0.5) half2

    // state: h as A fragment, c in f32 (row 0 half only)
    uint32_t a0 = 0u;
    float c00 = 0.f, c01 = 0.f;

    // IP(t) = x_t @ W_ih^T + bias in C-fragment layout (row 0 half)
    auto ip_build = [&](const float4 x0, uint32_t (&ip)[4]) {
        const uint32_t d00 = cvt_f16x2(x0.x, x0.x), d01 = cvt_f16x2(x0.y, x0.y);
        const uint32_t d02 = cvt_f16x2(x0.z, x0.z), d03 = cvt_f16x2(x0.w, x0.w);
#pragma unroll
        for (int gt = 0; gt < 4; ++gt) {
            uint32_t p = hfma2(d00, wih[gt][0], bias[gt]);
            p = hfma2(d01, wih[gt][1], p);
            p = hfma2(d02, wih[gt][2], p);
            ip[gt] = hfma2(d03, wih[gt][3], p);
        }
    };

    // rolling 4-step x prefetch
    float4 b0[4];
#pragma unroll
    for (int i = 0; i < 4; ++i) b0[i] = xp0[i];

    uint32_t ip[4];
    ip_build(b0[0], ip);                            // IP(0)

#pragma unroll 1
    for (int t0 = 0; t0 < T_SEQ; t0 += 4) {
        const int tn = (t0 + 4) & (T_SEQ - 1);
        float4 n0[4];
#pragma unroll
        for (int i = 0; i < 4; ++i) n0[i] = xp0[tn + i];

#pragma unroll
        for (int u = 0; u < 4; ++u) {
            // build IP(t+1) off-chain
            uint32_t ipn[4];
            ip_build((u < 3) ? b0[u + 1] : n0[0], ipn);

            // ---- 4 gate MMAs (k8, f16 D); row-half 1 duplicated/ignored ----
            uint32_t dI[2], dF[2], dG[2], dO[2];
            mma16808(dI, a0, a0, breg[0], ip[0], ip[0]);
            mma16808(dF, a0, a0, breg[1], ip[1], ip[1]);
            mma16808(dG, a0, a0, breg[2], ip[2], ip[2]);
            mma16808(dO, a0, a0, breg[3], ip[3], ip[3]);

            // ---- activations on row-half 0 only ----
            const uint32_t sI0 = hfma2(htanh2(dI[0]), K05, K05);
            const uint32_t sF0 = hfma2(htanh2(dF[0]), K05, K05);
            const uint32_t tG0 = htanh2(dG[0]);
            const uint32_t sO0 = hfma2(htanh2(dO[0]), K05, K05);

            // ---- c update in f32 ----
            const float2 iA = cvt_f32x2(sI0);
            const float2 fA = cvt_f32x2(sF0);
            const float2 gA = cvt_f32x2(tG0);
            c00 = fmaf(fA.x, c00, iA.x * gA.x);
            c01 = fmaf(fA.y, c01, iA.y * gA.y);

            // ---- h = o * tanh(c) -> next A fragment ----
            const uint32_t tc0 = htanh2(cvt_f16x2(c01, c00));
            a0 = hmul2(sO0, tc0);

            // rotate IP
#pragma unroll
            for (int gt = 0; gt < 4; ++gt) ip[gt] = ipn[gt];
        }

#pragma unroll
        for (int i = 0; i < 4; ++i) b0[i] = n0[i];
    }

    // ---- FC head: out[b] = sum_u h[b,u] * W_fc[u] + b_fc ----
    const float w0 = __ldg(W_fc + 2 * q);
    const float w1 = __ldg(W_fc + 2 * q + 1);
    const float2 h0 = cvt_f32x2(a0);
    float v0r = h0.x * w0 + h0.y * w1;
    v0r += __shfl_xor_sync(0xffffffffu, v0r, 1, 4);
    v0r += __shfl_xor_sync(0xffffffffu, v0r, 2, 4);

    if (q == 0 && v0) out[r0] = v0r + __ldg(b_fc);
}

extern "C" void kernel_launch(void* const* d_in, const int* in_sizes, int n_in,
                              void* d_out, int out_size)
{
    const float* x    = (const float*)d_in[0];
    const float* W_ih = (const float*)d_in[1];
    const float* W_hh = (const float*)d_in[2];
    const float* b_ih = (const float*)d_in[3];
    const float* b_hh = (const float*)d_in[4];
    const float* W_fc = (const float*)d_in[5];
    const float* b_fc = (const float*)d_in[6];
    float* out = (float*)d_out;

    const int B = in_sizes[0] / (T_SEQ * IDIM);     // 8192 here
    const int grid = (B + 7) / 8;                   // one warp per 8 batches

    lstm_mma_kernel<<<grid, 32>>>(x, W_ih, W_hh, b_ih, b_hh, W_fc, b_fc, out, B);
}

// round 15
// speedup vs baseline: 1.7721x; 1.0989x over previous
#include <cuda_runtime.h>
#include <cstdint>

// LSTM: B x T x I -> last hidden -> FC.  I=4, H=8, O=1, T=512.
// Round-15 = R14 (8 batch rows/warp, 1024 warps, k8 MMA + C-operand IP,
// f16-D == A-frag identity) with the cell state kept in FP16:
// the entire post-MMA tail is HFMA2/HMUL2/HTANH2 — the two ~20-cyc F2F
// converts at the f32-c boundary leave the serial chain (~144 -> ~80 cyc).
// Risk: fp16 c accumulation; predicted rel_err 4-7e-4 vs 1e-3 threshold.

#define T_SEQ 512
#define IDIM  4
#define HDIM  8

__device__ __forceinline__ uint32_t cvt_f16x2(float hi, float lo) {
    uint32_t r; asm("cvt.rn.f16x2.f32 %0, %1, %2;" : "=r"(r) : "f"(hi), "f"(lo)); return r;
}
__device__ __forceinline__ uint32_t htanh2(uint32_t a) {
    uint32_t d; asm("tanh.approx.f16x2 %0,%1;" : "=r"(d) : "r"(a)); return d;
}
__device__ __forceinline__ uint32_t hfma2(uint32_t a, uint32_t b, uint32_t c) {
    uint32_t d; asm("fma.rn.f16x2 %0,%1,%2,%3;" : "=r"(d) : "r"(a), "r"(b), "r"(c)); return d;
}
__device__ __forceinline__ uint32_t hmul2(uint32_t a, uint32_t b) {
    uint32_t d; asm("mul.rn.f16x2 %0,%1,%2;" : "=r"(d) : "r"(a), "r"(b)); return d;
}
__device__ __forceinline__ float2 cvt_f32x2(uint32_t p) {   // (lo, hi)
    float lo, hi;
    asm("{ .reg .f16 l, h; mov.b32 {l, h}, %2;"
        "  cvt.f32.f16 %0, l; cvt.f32.f16 %1, h; }"
        : "=f"(lo), "=f"(hi) : "r"(p));
    return make_float2(lo, hi);
}
// m16n8k8, f16 in / f16 out; C carries the precomputed input projection.
__device__ __forceinline__ void mma16808(uint32_t d[2],
                                         uint32_t a0, uint32_t a1, uint32_t b,
                                         uint32_t c0, uint32_t c1)
{
    asm("mma.sync.aligned.m16n8k8.row.col.f16.f16.f16.f16 "
        "{%0,%1}, {%2,%3}, {%4}, {%5,%6};"
        : "=r"(d[0]), "=r"(d[1])
        : "r"(a0), "r"(a1), "r"(b), "r"(c0), "r"(c1));
}

__global__ __launch_bounds__(32)
void lstm_mma_kernel(const float* __restrict__ x,
                     const float* __restrict__ W_ih,
                     const float* __restrict__ W_hh,
                     const float* __restrict__ b_ih,
                     const float* __restrict__ b_hh,
                     const float* __restrict__ W_fc,
                     const float* __restrict__ b_fc,
                     float* __restrict__ out,
                     int B)
{
    const int lane = threadIdx.x & 31;
    const int grp  = lane >> 2;                     // row group / B n-index
    const int q    = lane & 3;                      // col-pair selector

    const int base = blockIdx.x * 8;                // 8 batch rows per warp
    const int r0 = base + grp;
    const bool v0 = (r0 < B);
    const int r0c = v0 ? r0 : (B - 1);

    // ---- B fragments (k8 x n8, col-major), one per gate; sigmoid rows x0.5 ----
    uint32_t breg[4];
#pragma unroll
    for (int gt = 0; gt < 4; ++gt) {
        const float s = (gt == 2) ? 1.0f : 0.5f;
        const int row = gt * HDIM + grp;            // n = grp
        breg[gt] = cvt_f16x2(s * W_hh[row * HDIM + 2 * q + 1],
                             s * W_hh[row * HDIM + 2 * q]);
    }

    // ---- W_ih / bias in unit-pair f16x2 (lo = unit 2q, hi = unit 2q+1) ----
    uint32_t wih[4][IDIM], bias[4];
    {
        const int u0 = 2 * q, u1 = 2 * q + 1;
#pragma unroll
        for (int gt = 0; gt < 4; ++gt) {
            const float s = (gt == 2) ? 1.0f : 0.5f;
            const int ra = gt * HDIM + u0, rb = gt * HDIM + u1;
#pragma unroll
            for (int k = 0; k < IDIM; ++k)
                wih[gt][k] = cvt_f16x2(s * W_ih[rb * IDIM + k],
                                       s * W_ih[ra * IDIM + k]);
            bias[gt] = cvt_f16x2(s * (b_ih[rb] + b_hh[rb]),
                                 s * (b_ih[ra] + b_hh[ra]));
        }
    }

    const float4* __restrict__ xp0 =
        reinterpret_cast<const float4*>(x) + (size_t)r0c * T_SEQ;

    const uint32_t K05 = 0x38003800u;               // (0.5, 0.5) half2

    // state: h as A fragment (f16x2), c in f16x2 (units 2q, 2q+1)
    uint32_t a0 = 0u;
    uint32_t c16 = 0u;

    // IP(t) = x_t @ W_ih^T + bias in C-fragment layout (row 0 half)
    auto ip_build = [&](const float4 x0, uint32_t (&ip)[4]) {
        const uint32_t d00 = cvt_f16x2(x0.x, x0.x), d01 = cvt_f16x2(x0.y, x0.y);
        const uint32_t d02 = cvt_f16x2(x0.z, x0.z), d03 = cvt_f16x2(x0.w, x0.w);
#pragma unroll
        for (int gt = 0; gt < 4; ++gt) {
            uint32_t p = hfma2(d00, wih[gt][0], bias[gt]);
            p = hfma2(d01, wih[gt][1], p);
            p = hfma2(d02, wih[gt][2], p);
            ip[gt] = hfma2(d03, wih[gt][3], p);
        }
    };

    // rolling 4-step x prefetch
    float4 b0[4];
#pragma unroll
    for (int i = 0; i < 4; ++i) b0[i] = xp0[i];

    uint32_t ip[4];
    ip_build(b0[0], ip);                            // IP(0)

#pragma unroll 1
    for (int t0 = 0; t0 < T_SEQ; t0 += 4) {
        const int tn = (t0 + 4) & (T_SEQ - 1);
        float4 n0[4];
#pragma unroll
        for (int i = 0; i < 4; ++i) n0[i] = xp0[tn + i];

#pragma unroll
        for (int u = 0; u < 4; ++u) {
            // build IP(t+1) off-chain
            uint32_t ipn[4];
            ip_build((u < 3) ? b0[u + 1] : n0[0], ipn);

            // ---- 4 gate MMAs (k8, f16 D); row-half 1 duplicated/ignored ----
            uint32_t dI[2], dF[2], dG[2], dO[2];
            mma16808(dI, a0, a0, breg[0], ip[0], ip[0]);
            mma16808(dF, a0, a0, breg[1], ip[1], ip[1]);
            mma16808(dG, a0, a0, breg[2], ip[2], ip[2]);
            mma16808(dO, a0, a0, breg[3], ip[3], ip[3]);

            // ---- all-f16 tail: activations + cell + hidden ----
            const uint32_t sI0 = hfma2(htanh2(dI[0]), K05, K05);   // i
            const uint32_t sF0 = hfma2(htanh2(dF[0]), K05, K05);   // f
            const uint32_t tG0 = htanh2(dG[0]);                    // g
            const uint32_t sO0 = hfma2(htanh2(dO[0]), K05, K05);   // o

            c16 = hfma2(sF0, c16, hmul2(sI0, tG0));  // c = f*c + i*g   (fp16)
            a0  = hmul2(sO0, htanh2(c16));           // h = o * tanh(c) -> next A

            // rotate IP
#pragma unroll
            for (int gt = 0; gt < 4; ++gt) ip[gt] = ipn[gt];
        }

#pragma unroll
        for (int i = 0; i < 4; ++i) b0[i] = n0[i];
    }

    // ---- FC head: out[b] = sum_u h[b,u] * W_fc[u] + b_fc ----
    const float w0 = __ldg(W_fc + 2 * q);
    const float w1 = __ldg(W_fc + 2 * q + 1);
    const float2 h0 = cvt_f32x2(a0);
    float v0r = h0.x * w0 + h0.y * w1;
    v0r += __shfl_xor_sync(0xffffffffu, v0r, 1, 4);
    v0r += __shfl_xor_sync(0xffffffffu, v0r, 2, 4);

    if (q == 0 && v0) out[r0] = v0r + __ldg(b_fc);
}

extern "C" void kernel_launch(void* const* d_in, const int* in_sizes, int n_in,
                              void* d_out, int out_size)
{
    const float* x    = (const float*)d_in[0];
    const float* W_ih = (const float*)d_in[1];
    const float* W_hh = (const float*)d_in[2];
    const float* b_ih = (const float*)d_in[3];
    const float* b_hh = (const float*)d_in[4];
    const float* W_fc = (const float*)d_in[5];
    const float* b_fc = (const float*)d_in[6];
    float* out = (float*)d_out;

    const int B = in_sizes[0] / (T_SEQ * IDIM);     // 8192 here
    const int grid = (B + 7) / 8;                   // one warp per 8 batches

    lstm_mma_kernel<<<grid, 32>>>(x, W_ih, W_hh, b_ih, b_hh, W_fc, b_fc, out, B);
}